// round 2
// baseline (speedup 1.0000x reference)
#include <cuda_runtime.h>

#define BB 8
#define NN 2048
#define DD 64
#define HH 64
#define CC 16
#define NROW (BB*NN)      /* 16384 */
#define NMASK (NROW*HH)   /* 1048576 */

typedef unsigned long long ull;

// ---- scratch (static device globals; no allocation) ----
__device__ float g_dis[NROW];          // d^-1/2 per (b,row)
__device__ float g_M1[NROW*HH];        // d_j * (X @ W1)
__device__ float g_Hd[NROW*HH];        // layer1 output after relu+dropout
__device__ float g_M2[NROW*CC];        // d_j * (Hd @ W2)
__device__ float g_mask[NMASK];        // dropout multiplier: 0.0 or 2.0

// ---- packed f32x2 helpers (Blackwell FFMA2) ----
__device__ __forceinline__ ull f2pack(float a, float b) {
    ull r; asm("mov.b64 %0, {%1,%2};" : "=l"(r) : "f"(a), "f"(b)); return r;
}
__device__ __forceinline__ ull f2fma(ull a, ull b, ull c) {
    ull r; asm("fma.rn.f32x2 %0, %1, %2, %3;" : "=l"(r) : "l"(a), "l"(b), "l"(c)); return r;
}
__device__ __forceinline__ float2 f2unpack(ull v) {
    float2 r; asm("mov.b64 {%0,%1}, %2;" : "=f"(r.x), "=f"(r.y) : "l"(v)); return r;
}

// ============================================================
// 1) degrees: g_dis[row] = (sum_j A[row,j] + 1)^-1/2
// ============================================================
__global__ void k_degree(const float* __restrict__ A) {
    int row = blockIdx.x;                       // 0..16383
    const float4* p = reinterpret_cast<const float4*>(A + (size_t)row * NN);
    int t = threadIdx.x;                        // 128 threads
    float s = 0.f;
    #pragma unroll
    for (int i = 0; i < 4; i++) {
        float4 v = p[t + i * 128];
        s += (v.x + v.y) + (v.z + v.w);
    }
    #pragma unroll
    for (int o = 16; o; o >>= 1) s += __shfl_xor_sync(0xffffffffu, s, o);
    __shared__ float ws[4];
    if ((t & 31) == 0) ws[t >> 5] = s;
    __syncthreads();
    if (t == 0) g_dis[row] = rsqrtf(((ws[0] + ws[1]) + (ws[2] + ws[3])) + 1.0f);
}

// ============================================================
// 2) dropout mask: JAX *partitionable* threefry (default since 0.4.36).
//    Per flat index i: (o0,o1) = threefry2x32(key=(0,42), x=(i>>32, i&0xffffffff))
//    bits = o0 ^ o1 ; keep <=> top bit clear -> mask 2.0 else 0.0
// ============================================================
__global__ void k_mask() {
    unsigned i = blockIdx.x * 256u + threadIdx.x;   // 0..1048575
    unsigned x0 = 0u;        // hi 32 bits of 64-bit counter (zero here)
    unsigned x1 = i;         // lo 32 bits
    const unsigned ks0 = 0u, ks1 = 42u, ks2 = 0x1BD11BDAu ^ 0u ^ 42u;
    x0 += ks0; x1 += ks1;
#define TFR(r) { x0 += x1; x1 = (x1 << (r)) | (x1 >> (32 - (r))); x1 ^= x0; }
    TFR(13) TFR(15) TFR(26) TFR(6)
    x0 += ks1; x1 += ks2 + 1u;
    TFR(17) TFR(29) TFR(16) TFR(24)
    x0 += ks2; x1 += ks0 + 2u;
    TFR(13) TFR(15) TFR(26) TFR(6)
    x0 += ks0; x1 += ks1 + 3u;
    TFR(17) TFR(29) TFR(16) TFR(24)
    x0 += ks1; x1 += ks2 + 4u;
    TFR(13) TFR(15) TFR(26) TFR(6)
    x0 += ks2; x1 += ks0 + 5u;
#undef TFR
    unsigned bits = x0 ^ x1;
    g_mask[i] = (bits >> 31) ? 0.0f : 2.0f;
}

// ============================================================
// 3) M1[row,h] = g_dis[row] * sum_d X[row,d] * W1[d,h]
// ============================================================
__global__ void k_xw1(const float* __restrict__ X, const float* __restrict__ W1) {
    __shared__ float Ws[DD * HH];
    int t = threadIdx.x;                        // 256
    for (int i = t; i < DD * HH; i += 256) Ws[i] = W1[i];
    __syncthreads();
    int h = t & 63, rl = t >> 6;
    int row0 = blockIdx.x * 32;
    for (int rr = rl; rr < 32; rr += 4) {
        int row = row0 + rr;
        const float4* x4 = reinterpret_cast<const float4*>(X + (size_t)row * DD);
        float s = 0.f;
        #pragma unroll
        for (int d4 = 0; d4 < 16; d4++) {
            float4 v = x4[d4];
            s += v.x * Ws[(d4 * 4 + 0) * HH + h];
            s += v.y * Ws[(d4 * 4 + 1) * HH + h];
            s += v.z * Ws[(d4 * 4 + 2) * HH + h];
            s += v.w * Ws[(d4 * 4 + 3) * HH + h];
        }
        g_M1[(size_t)row * HH + h] = g_dis[row] * s;
    }
}

// ============================================================
// 4) layer1: Hd[i,h] = mask * relu(d_i * sum_j Atil[i,j]*M1[j,h] + b1[h])
//    block tile: 128 rows x 64 cols, 128 threads, 8x8 per thread (f32x2)
// ============================================================
__global__ __launch_bounds__(128) void k_layer1(const float* __restrict__ A,
                                                const float* __restrict__ b1v) {
    __shared__ float As[128][36];   // [row][k], pad keeps rg-strided reads conflict-free
    __shared__ float Bs[32][64];    // [k][h]
    const int b  = blockIdx.y;
    const int i0 = blockIdx.x * 128;
    const int t  = threadIdx.x;
    const int cg = t & 7;           // cols cg*8 .. cg*8+7
    const int rg = t >> 3;          // rows rg + 16*r  (r = 0..7)
    const float* Ab = A + ((size_t)(b * NN + i0)) * NN;

    ull acc[8][4];
    #pragma unroll
    for (int r = 0; r < 8; r++)
        #pragma unroll
        for (int c = 0; c < 4; c++) acc[r][c] = 0ull;

    for (int k0 = 0; k0 < NN; k0 += 32) {
        #pragma unroll
        for (int it = 0; it < 8; it++) {        // A tile 128x32 (1024 float4)
            int idx = it * 128 + t;
            int row = idx >> 3, f4 = idx & 7;
            float4 v = *reinterpret_cast<const float4*>(Ab + (size_t)row * NN + k0 + f4 * 4);
            *reinterpret_cast<float4*>(&As[row][f4 * 4]) = v;
        }
        #pragma unroll
        for (int it = 0; it < 4; it++) {        // B tile 32x64 (512 float4)
            int idx = it * 128 + t;
            int kk = idx >> 4, f4 = idx & 15;
            float4 v = *reinterpret_cast<const float4*>(g_M1 + ((size_t)(b * NN + k0 + kk)) * HH + f4 * 4);
            *reinterpret_cast<float4*>(&Bs[kk][f4 * 4]) = v;
        }
        __syncthreads();
        {   // A_tilde = A + I
            int jj = i0 + t - k0;
            if (jj >= 0 && jj < 32) As[t][jj] += 1.0f;
        }
        __syncthreads();
        #pragma unroll 8
        for (int kk = 0; kk < 32; kk++) {
            const ull* bp = reinterpret_cast<const ull*>(&Bs[kk][cg * 8]);
            ull b0 = bp[0], b1 = bp[1], b2 = bp[2], b3 = bp[3];
            #pragma unroll
            for (int r = 0; r < 8; r++) {
                float a = As[rg + 16 * r][kk];
                ull aa = f2pack(a, a);
                acc[r][0] = f2fma(aa, b0, acc[r][0]);
                acc[r][1] = f2fma(aa, b1, acc[r][1]);
                acc[r][2] = f2fma(aa, b2, acc[r][2]);
                acc[r][3] = f2fma(aa, b3, acc[r][3]);
            }
        }
        __syncthreads();
    }
    // epilogue: scale by d_i, +bias, relu, dropout
    float bias[8];
    #pragma unroll
    for (int q = 0; q < 8; q++) bias[q] = b1v[cg * 8 + q];
    #pragma unroll
    for (int r = 0; r < 8; r++) {
        int gi = b * NN + i0 + rg + 16 * r;
        float di = g_dis[gi];
        size_t base = (size_t)gi * HH + cg * 8;
        #pragma unroll
        for (int c = 0; c < 4; c++) {
            float2 v = f2unpack(acc[r][c]);
            float o0 = fmaxf(di * v.x + bias[c * 2 + 0], 0.f);
            float o1 = fmaxf(di * v.y + bias[c * 2 + 1], 0.f);
            o0 *= g_mask[base + c * 2];
            o1 *= g_mask[base + c * 2 + 1];
            *reinterpret_cast<float2*>(&g_Hd[base + c * 2]) = make_float2(o0, o1);
        }
    }
}

// ============================================================
// 5) M2[row,c] = g_dis[row] * sum_h Hd[row,h] * W2[h,c]
// ============================================================
__global__ void k_hw2(const float* __restrict__ W2) {
    __shared__ float Ws[DD * CC];
    int t = threadIdx.x;                        // 256
    for (int i = t; i < DD * CC; i += 256) Ws[i] = W2[i];
    __syncthreads();
    int c = t & 15, rl = t >> 4;
    int row = blockIdx.x * 16 + rl;
    const float4* h4 = reinterpret_cast<const float4*>(g_Hd + (size_t)row * HH);
    float s = 0.f;
    #pragma unroll
    for (int d4 = 0; d4 < 16; d4++) {
        float4 v = h4[d4];
        s += v.x * Ws[(d4 * 4 + 0) * CC + c] + v.y * Ws[(d4 * 4 + 1) * CC + c]
           + v.z * Ws[(d4 * 4 + 2) * CC + c] + v.w * Ws[(d4 * 4 + 3) * CC + c];
    }
    g_M2[(size_t)row * CC + c] = g_dis[row] * s;
}

// ============================================================
// 6) layer2: out[i,c] = d_i * sum_j Atil[i,j]*M2[j,c] + b2[c]
//    block tile: 128 rows x 16 cols, 128 threads, 8 rows x 2 cols/thread
// ============================================================
__global__ __launch_bounds__(128) void k_layer2(const float* __restrict__ A,
                                                const float* __restrict__ b2v,
                                                float* __restrict__ out) {
    __shared__ float As[128][68];
    __shared__ float Bs[64][16];
    const int b  = blockIdx.y;
    const int i0 = blockIdx.x * 128;
    const int t  = threadIdx.x;
    const int cp = t & 7;           // cols 2*cp, 2*cp+1
    const int rg = t >> 3;          // rows rg + 16*r
    const float* Ab = A + ((size_t)(b * NN + i0)) * NN;

    ull acc[8];
    #pragma unroll
    for (int r = 0; r < 8; r++) acc[r] = 0ull;

    for (int k0 = 0; k0 < NN; k0 += 64) {
        #pragma unroll
        for (int it = 0; it < 16; it++) {       // A tile 128x64 (2048 float4)
            int idx = it * 128 + t;
            int row = idx >> 4, f4 = idx & 15;
            float4 v = *reinterpret_cast<const float4*>(Ab + (size_t)row * NN + k0 + f4 * 4);
            *reinterpret_cast<float4*>(&As[row][f4 * 4]) = v;
        }
        #pragma unroll
        for (int it = 0; it < 2; it++) {        // B tile 64x16 (256 float4)
            int idx = it * 128 + t;
            int kk = idx >> 2, f4 = idx & 3;
            float4 v = *reinterpret_cast<const float4*>(g_M2 + ((size_t)(b * NN + k0 + kk)) * CC + f4 * 4);
            *reinterpret_cast<float4*>(&Bs[kk][f4 * 4]) = v;
        }
        __syncthreads();
        {
            int jj = i0 + t - k0;
            if (jj >= 0 && jj < 64) As[t][jj] += 1.0f;
        }
        __syncthreads();
        #pragma unroll 8
        for (int kk = 0; kk < 64; kk++) {
            ull bb = *reinterpret_cast<const ull*>(&Bs[kk][cp * 2]);
            #pragma unroll
            for (int r = 0; r < 8; r++) {
                float a = As[rg + 16 * r][kk];
                acc[r] = f2fma(f2pack(a, a), bb, acc[r]);
            }
        }
        __syncthreads();
    }
    float bz0 = b2v[cp * 2], bz1 = b2v[cp * 2 + 1];
    #pragma unroll
    for (int r = 0; r < 8; r++) {
        int gi = b * NN + i0 + rg + 16 * r;
        float di = g_dis[gi];
        float2 v = f2unpack(acc[r]);
        *reinterpret_cast<float2*>(&out[(size_t)gi * CC + cp * 2]) =
            make_float2(di * v.x + bz0, di * v.y + bz1);
    }
}

// ============================================================
extern "C" void kernel_launch(void* const* d_in, const int* in_sizes, int n_in,
                              void* d_out, int out_size) {
    const float* X  = (const float*)d_in[0];
    const float* A  = (const float*)d_in[1];
    const float* W1 = (const float*)d_in[2];
    const float* b1 = (const float*)d_in[3];
    const float* W2 = (const float*)d_in[4];
    const float* b2 = (const float*)d_in[5];
    float* out = (float*)d_out;

    k_degree<<<NROW, 128>>>(A);
    k_mask<<<NMASK / 256, 256>>>();
    k_xw1<<<NROW / 32, 256>>>(X, W1);
    k_layer1<<<dim3(NN / 128, BB), 128>>>(A, b1);
    k_hw2<<<NROW / 16, 256>>>(W2);
    k_layer2<<<dim3(NN / 128, BB), 128>>>(A, b2, out);
}

// round 3
// speedup vs baseline: 1.6155x; 1.6155x over previous
#include <cuda_runtime.h>

#define BB 8
#define NN 2048
#define DD 64
#define HH 64
#define CC 16
#define NROW (BB*NN)      /* 16384 */
#define NMASK (NROW*HH)   /* 1048576 */
#define KS 4              /* k-split factor */
#define KC1 (NN/KS)       /* 512: K-chunk layer kernels */

typedef unsigned long long ull;

// ---- scratch (static device globals; no allocation) ----
__device__ float g_dis[NROW];            // d^-1/2 per (b,row)
__device__ float g_M1[NROW*HH];          // d_j * (X @ W1)
__device__ float g_Hd[NROW*HH];          // layer1 output after relu+dropout
__device__ float g_M2[NROW*CC];          // d_j * (Hd @ W2)
__device__ float g_mask[NMASK];          // dropout multiplier: 0.0 or 2.0
__device__ float g_p1[KS][NROW*HH];      // layer1 k-split partials (16 MB)
__device__ float g_p2[KS][NROW*CC];      // layer2 k-split partials (4 MB)

// ---- packed f32x2 helpers (Blackwell FFMA2) ----
__device__ __forceinline__ ull f2pack(float a, float b) {
    ull r; asm("mov.b64 %0, {%1,%2};" : "=l"(r) : "f"(a), "f"(b)); return r;
}
__device__ __forceinline__ ull f2fma(ull a, ull b, ull c) {
    ull r; asm("fma.rn.f32x2 %0, %1, %2, %3;" : "=l"(r) : "l"(a), "l"(b), "l"(c)); return r;
}
__device__ __forceinline__ float2 f2unpack(ull v) {
    float2 r; asm("mov.b64 {%0,%1}, %2;" : "=f"(r.x), "=f"(r.y) : "l"(v)); return r;
}

// ============================================================
// 1) degrees: g_dis[row] = (sum_j A[row,j] + 1)^-1/2
// ============================================================
__global__ void k_degree(const float* __restrict__ A) {
    int row = blockIdx.x;
    const float4* p = reinterpret_cast<const float4*>(A + (size_t)row * NN);
    int t = threadIdx.x;                        // 128
    float s = 0.f;
    #pragma unroll
    for (int i = 0; i < 4; i++) {
        float4 v = p[t + i * 128];
        s += (v.x + v.y) + (v.z + v.w);
    }
    #pragma unroll
    for (int o = 16; o; o >>= 1) s += __shfl_xor_sync(0xffffffffu, s, o);
    __shared__ float ws[4];
    if ((t & 31) == 0) ws[t >> 5] = s;
    __syncthreads();
    if (t == 0) g_dis[row] = rsqrtf(((ws[0] + ws[1]) + (ws[2] + ws[3])) + 1.0f);
}

// ============================================================
// 2) dropout mask: JAX partitionable threefry, key=(0,42)
// ============================================================
__global__ void k_mask() {
    unsigned i = blockIdx.x * 256u + threadIdx.x;
    unsigned x0 = 0u, x1 = i;
    const unsigned ks0 = 0u, ks1 = 42u, ks2 = 0x1BD11BDAu ^ 0u ^ 42u;
    x0 += ks0; x1 += ks1;
#define TFR(r) { x0 += x1; x1 = (x1 << (r)) | (x1 >> (32 - (r))); x1 ^= x0; }
    TFR(13) TFR(15) TFR(26) TFR(6)
    x0 += ks1; x1 += ks2 + 1u;
    TFR(17) TFR(29) TFR(16) TFR(24)
    x0 += ks2; x1 += ks0 + 2u;
    TFR(13) TFR(15) TFR(26) TFR(6)
    x0 += ks0; x1 += ks1 + 3u;
    TFR(17) TFR(29) TFR(16) TFR(24)
    x0 += ks1; x1 += ks2 + 4u;
    TFR(13) TFR(15) TFR(26) TFR(6)
    x0 += ks2; x1 += ks0 + 5u;
#undef TFR
    g_mask[i] = ((x0 ^ x1) >> 31) ? 0.0f : 2.0f;
}

// ============================================================
// 3) M1[row,h] = g_dis[row] * sum_d X[row,d] * W1[d,h]
// ============================================================
__global__ void k_xw1(const float* __restrict__ X, const float* __restrict__ W1) {
    __shared__ float Ws[DD * HH];
    int t = threadIdx.x;                        // 256
    for (int i = t; i < DD * HH; i += 256) Ws[i] = W1[i];
    __syncthreads();
    int h = t & 63, rl = t >> 6;
    int row0 = blockIdx.x * 32;
    for (int rr = rl; rr < 32; rr += 4) {
        int row = row0 + rr;
        const float4* x4 = reinterpret_cast<const float4*>(X + (size_t)row * DD);
        float s = 0.f;
        #pragma unroll
        for (int d4 = 0; d4 < 16; d4++) {
            float4 v = x4[d4];
            s += v.x * Ws[(d4 * 4 + 0) * HH + h];
            s += v.y * Ws[(d4 * 4 + 1) * HH + h];
            s += v.z * Ws[(d4 * 4 + 2) * HH + h];
            s += v.w * Ws[(d4 * 4 + 3) * HH + h];
        }
        g_M1[(size_t)row * HH + h] = g_dis[row] * s;
    }
}

// ============================================================
// 4) layer1 matmul partials (k-split): p1[kc][i,h] = sum_{j in chunk} A[i,j]*M1[j,h]
//    tile 128x64, 128 threads, 8x8 per thread (f32x2), K chunk 512
// ============================================================
__global__ __launch_bounds__(128) void k_layer1(const float* __restrict__ A) {
    __shared__ float As[128][36];
    __shared__ float Bs[32][64];
    const int b  = blockIdx.y;
    const int i0 = blockIdx.x * 128;
    const int kc = blockIdx.z;
    const int t  = threadIdx.x;
    const int cg = t & 7;
    const int rg = t >> 3;
    const float* Ab = A + ((size_t)(b * NN + i0)) * NN;

    ull acc[8][4];
    #pragma unroll
    for (int r = 0; r < 8; r++)
        #pragma unroll
        for (int c = 0; c < 4; c++) acc[r][c] = 0ull;

    const int kend = kc * KC1 + KC1;
    for (int k0 = kc * KC1; k0 < kend; k0 += 32) {
        #pragma unroll
        for (int it = 0; it < 8; it++) {        // A tile 128x32
            int idx = it * 128 + t;
            int row = idx >> 3, f4 = idx & 7;
            float4 v = *reinterpret_cast<const float4*>(Ab + (size_t)row * NN + k0 + f4 * 4);
            *reinterpret_cast<float4*>(&As[row][f4 * 4]) = v;
        }
        #pragma unroll
        for (int it = 0; it < 4; it++) {        // B tile 32x64
            int idx = it * 128 + t;
            int kk = idx >> 4, f4 = idx & 15;
            float4 v = *reinterpret_cast<const float4*>(g_M1 + ((size_t)(b * NN + k0 + kk)) * HH + f4 * 4);
            *reinterpret_cast<float4*>(&Bs[kk][f4 * 4]) = v;
        }
        __syncthreads();
        #pragma unroll 8
        for (int kk = 0; kk < 32; kk++) {
            const ull* bp = reinterpret_cast<const ull*>(&Bs[kk][cg * 8]);
            ull b0 = bp[0], b1 = bp[1], b2 = bp[2], b3 = bp[3];
            #pragma unroll
            for (int r = 0; r < 8; r++) {
                float a = As[rg + 16 * r][kk];
                ull aa = f2pack(a, a);
                acc[r][0] = f2fma(aa, b0, acc[r][0]);
                acc[r][1] = f2fma(aa, b1, acc[r][1]);
                acc[r][2] = f2fma(aa, b2, acc[r][2]);
                acc[r][3] = f2fma(aa, b3, acc[r][3]);
            }
        }
        __syncthreads();
    }
    float* P = g_p1[kc];
    #pragma unroll
    for (int r = 0; r < 8; r++) {
        int gi = b * NN + i0 + rg + 16 * r;
        size_t base = (size_t)gi * HH + cg * 8;
        #pragma unroll
        for (int c = 0; c < 4; c++) {
            float2 v = f2unpack(acc[r][c]);
            *reinterpret_cast<float2*>(&P[base + c * 2]) = make_float2(v.x, v.y);
        }
    }
}

// ============================================================
// 4b) epilogue1: Hd = mask * relu(d_i*(sum_kc p1 + M1[i,:]) + b1)
//     (the +M1[i,:] term is the A_tilde identity diagonal)
// ============================================================
__global__ void k_ep1(const float* __restrict__ b1v) {
    int i4 = blockIdx.x * 256 + threadIdx.x;    // float4 index, 0..262143
    int row = i4 >> 4;
    int h = (i4 & 15) * 4;
    const float4* m1 = reinterpret_cast<const float4*>(g_M1);
    float4 s = m1[i4];
    #pragma unroll
    for (int kc = 0; kc < KS; kc++) {
        float4 p = reinterpret_cast<const float4*>(g_p1[kc])[i4];
        s.x += p.x; s.y += p.y; s.z += p.z; s.w += p.w;
    }
    float di = g_dis[row];
    float4 bz = *reinterpret_cast<const float4*>(b1v + h);
    float4 mk = reinterpret_cast<const float4*>(g_mask)[i4];
    float4 o;
    o.x = fmaxf(di * s.x + bz.x, 0.f) * mk.x;
    o.y = fmaxf(di * s.y + bz.y, 0.f) * mk.y;
    o.z = fmaxf(di * s.z + bz.z, 0.f) * mk.z;
    o.w = fmaxf(di * s.w + bz.w, 0.f) * mk.w;
    reinterpret_cast<float4*>(g_Hd)[i4] = o;
}

// ============================================================
// 5) M2[row,c] = g_dis[row] * sum_h Hd[row,h] * W2[h,c]
// ============================================================
__global__ void k_hw2(const float* __restrict__ W2) {
    __shared__ float Ws[DD * CC];
    int t = threadIdx.x;                        // 256
    for (int i = t; i < DD * CC; i += 256) Ws[i] = W2[i];
    __syncthreads();
    int c = t & 15, rl = t >> 4;
    int row = blockIdx.x * 16 + rl;
    const float4* h4 = reinterpret_cast<const float4*>(g_Hd + (size_t)row * HH);
    float s = 0.f;
    #pragma unroll
    for (int d4 = 0; d4 < 16; d4++) {
        float4 v = h4[d4];
        s += v.x * Ws[(d4 * 4 + 0) * CC + c] + v.y * Ws[(d4 * 4 + 1) * CC + c]
           + v.z * Ws[(d4 * 4 + 2) * CC + c] + v.w * Ws[(d4 * 4 + 3) * CC + c];
    }
    g_M2[(size_t)row * CC + c] = g_dis[row] * s;
}

// ============================================================
// 6) layer2 matmul partials (k-split): p2[kc][i,c] = sum_{j in chunk} A[i,j]*M2[j,c]
//    tile 128x16, 128 threads, 8 rows x 2 cols per thread, K chunk 512
// ============================================================
__global__ __launch_bounds__(128) void k_layer2(const float* __restrict__ A) {
    __shared__ float As[128][68];
    __shared__ float Bs[64][16];
    const int b  = blockIdx.y;
    const int i0 = blockIdx.x * 128;
    const int kc = blockIdx.z;
    const int t  = threadIdx.x;
    const int cp = t & 7;
    const int rg = t >> 3;
    const float* Ab = A + ((size_t)(b * NN + i0)) * NN;

    ull acc[8];
    #pragma unroll
    for (int r = 0; r < 8; r++) acc[r] = 0ull;

    const int kend = kc * KC1 + KC1;
    for (int k0 = kc * KC1; k0 < kend; k0 += 64) {
        #pragma unroll
        for (int it = 0; it < 16; it++) {       // A tile 128x64
            int idx = it * 128 + t;
            int row = idx >> 4, f4 = idx & 15;
            float4 v = *reinterpret_cast<const float4*>(Ab + (size_t)row * NN + k0 + f4 * 4);
            *reinterpret_cast<float4*>(&As[row][f4 * 4]) = v;
        }
        #pragma unroll
        for (int it = 0; it < 2; it++) {        // B tile 64x16
            int idx = it * 128 + t;
            int kk = idx >> 2, f4 = idx & 3;
            float4 v = *reinterpret_cast<const float4*>(g_M2 + ((size_t)(b * NN + k0 + kk)) * CC + f4 * 4);
            *reinterpret_cast<float4*>(&Bs[kk][f4 * 4]) = v;
        }
        __syncthreads();
        #pragma unroll 8
        for (int kk = 0; kk < 64; kk++) {
            ull bb = *reinterpret_cast<const ull*>(&Bs[kk][cp * 2]);
            #pragma unroll
            for (int r = 0; r < 8; r++) {
                float a = As[rg + 16 * r][kk];
                acc[r] = f2fma(f2pack(a, a), bb, acc[r]);
            }
        }
        __syncthreads();
    }
    float* P = g_p2[kc];
    #pragma unroll
    for (int r = 0; r < 8; r++) {
        int gi = b * NN + i0 + rg + 16 * r;
        float2 v = f2unpack(acc[r]);
        *reinterpret_cast<float2*>(&P[(size_t)gi * CC + cp * 2]) = make_float2(v.x, v.y);
    }
}

// ============================================================
// 6b) epilogue2: out = d_i*(sum_kc p2 + M2[i,:]) + b2
// ============================================================
__global__ void k_ep2(const float* __restrict__ b2v, float* __restrict__ out) {
    int i4 = blockIdx.x * 256 + threadIdx.x;    // float4 index, 0..65535
    int row = i4 >> 2;
    int c = (i4 & 3) * 4;
    float4 s = reinterpret_cast<const float4*>(g_M2)[i4];
    #pragma unroll
    for (int kc = 0; kc < KS; kc++) {
        float4 p = reinterpret_cast<const float4*>(g_p2[kc])[i4];
        s.x += p.x; s.y += p.y; s.z += p.z; s.w += p.w;
    }
    float di = g_dis[row];
    float4 bz = *reinterpret_cast<const float4*>(b2v + c);
    float4 o;
    o.x = di * s.x + bz.x;
    o.y = di * s.y + bz.y;
    o.z = di * s.z + bz.z;
    o.w = di * s.w + bz.w;
    reinterpret_cast<float4*>(out)[i4] = o;
}

// ============================================================
extern "C" void kernel_launch(void* const* d_in, const int* in_sizes, int n_in,
                              void* d_out, int out_size) {
    const float* X  = (const float*)d_in[0];
    const float* A  = (const float*)d_in[1];
    const float* W1 = (const float*)d_in[2];
    const float* b1 = (const float*)d_in[3];
    const float* W2 = (const float*)d_in[4];
    const float* b2 = (const float*)d_in[5];
    float* out = (float*)d_out;

    k_degree<<<NROW, 128>>>(A);
    k_mask<<<NMASK / 256, 256>>>();
    k_xw1<<<NROW / 32, 256>>>(X, W1);
    k_layer1<<<dim3(NN / 128, BB, KS), 128>>>(A);
    k_ep1<<<NMASK / 4 / 256, 256>>>(b1);
    k_hw2<<<NROW / 16, 256>>>(W2);
    k_layer2<<<dim3(NN / 128, BB, KS), 128>>>(A);
    k_ep2<<<NROW * CC / 4 / 256, 256>>>(b2, out);
}